// round 14
// baseline (speedup 1.0000x reference)
#include <cuda_runtime.h>
#include <cuda_bf16.h>

// ---------------------------------------------------------------------------
// NeuralODE Dopri5, R14: fused-weight single-GEMM stages with role-split warps.
//   Z := y@W1+b1 (Q-warp regs), Q_q := k_q@W1. W21 := W2@W1 (prep, fp32).
//   Stage: Hc (Q-warps: H = tanh(Z + dt*sum a_q Q_q)) -> BAR -> fused GEMM
//   H @ [W2t | W21t] -> [k | Q]. k folded into y on the fly (k-warp regs).
//   Q: latest in regs, older in warp-private conflict-free smem (no syncs).
//   One barrier per stage (6/step). 256 thr, 8 warps, 32m x 64n tiles.
// ---------------------------------------------------------------------------

#define PADK 136
#define HT   (64 * PADK * 2)            // H tile = 17408 B
typedef __nv_bfloat16 Row[PADK];

__device__ float g_dt0;
__device__ float g_W21[128 * 128];      // [n][hid] = W21[hid][n], fp32
__device__ float g_bQ[128];             // b2 @ W1

__device__ __forceinline__ unsigned cvt_bf2u(float lo, float hi) {
    unsigned r; asm("cvt.rn.bf16x2.f32 %0, %1, %2;" : "=r"(r) : "f"(hi), "f"(lo)); return r;
}
__device__ __forceinline__ unsigned tanh_bf2(unsigned p) {
    unsigned r; asm("tanh.approx.bf16x2 %0, %1;" : "=r"(r) : "r"(p)); return r;
}
__device__ __forceinline__ float lo16f(unsigned u) { return __uint_as_float(u << 16); }
__device__ __forceinline__ float hi16f(unsigned u) { return __uint_as_float(u & 0xFFFF0000u); }
__device__ __forceinline__ __nv_bfloat162 asbf2(unsigned u) {
    return *reinterpret_cast<__nv_bfloat162*>(&u);
}
__device__ __forceinline__ void mma_bf16(float* c, const unsigned* a, const unsigned* b) {
    asm volatile("mma.sync.aligned.m16n8k16.row.col.f32.bf16.bf16.f32 "
                 "{%0,%1,%2,%3}, {%4,%5,%6,%7}, {%8,%9}, {%0,%1,%2,%3};"
                 : "+f"(c[0]), "+f"(c[1]), "+f"(c[2]), "+f"(c[3])
                 : "r"(a[0]), "r"(a[1]), "r"(a[2]), "r"(a[3]), "r"(b[0]), "r"(b[1]));
}
__device__ __forceinline__ void ldsm_x4(unsigned a[4], unsigned addr) {
    asm volatile("ldmatrix.sync.aligned.m8n8.x4.shared.b16 {%0,%1,%2,%3}, [%4];"
                 : "=r"(a[0]), "=r"(a[1]), "=r"(a[2]), "=r"(a[3]) : "r"(addr));
}

// C[32x64] = A[32x128] @ B(64 rows)^T + bias. A,B via ldmatrix.
__device__ __forceinline__ void gemmF(float c[2][8][4], unsigned abase,
                                      unsigned bbase, const float* bias, int qn) {
#pragma unroll
    for (int nt = 0; nt < 8; nt++) {
        float b0 = bias[nt * 8 + qn * 2], b1v = bias[nt * 8 + qn * 2 + 1];
#pragma unroll
        for (int mt = 0; mt < 2; mt++) {
            c[mt][nt][0] = c[mt][nt][2] = b0;
            c[mt][nt][1] = c[mt][nt][3] = b1v;
        }
    }
#pragma unroll
    for (int kk = 0; kk < 8; kk++) {
        unsigned a[2][4], b[4][4];
#pragma unroll
        for (int mt = 0; mt < 2; mt++)
            ldsm_x4(a[mt], abase + mt * (16 * PADK * 2) + kk * 32);
#pragma unroll
        for (int g = 0; g < 4; g++)
            ldsm_x4(b[g], bbase + g * (16 * PADK * 2) + kk * 32);
#pragma unroll
        for (int mt = 0; mt < 2; mt++)
#pragma unroll
            for (int g = 0; g < 4; g++) {
                mma_bf16(c[mt][2 * g],     a[mt], b[g]);
                mma_bf16(c[mt][2 * g + 1], a[mt], b[g] + 2);
            }
    }
}

// Q-warp: H = tanh(Z + dt * sum_{q<S} a_q Q_q). Q_{S-1} from regs, older smem.
template <int S>
__device__ __forceinline__ void hc(Row* Hp, const float (&Z)[2][8][4],
                                   const unsigned (&qlast)[32], const unsigned* qb,
                                   float dt, const __nv_bfloat162* kc,
                                   int m0, int hn0, int gm, int qn) {
#pragma unroll
    for (int mt = 0; mt < 2; mt++)
#pragma unroll
        for (int nt = 0; nt < 8; nt++)
#pragma unroll
            for (int h = 0; h < 2; h++) {
                const int idx = (mt * 8 + nt) * 2 + h;
                const int rp = mt * 16 + gm + 8 * h;
                const int j2 = (hn0 >> 1) + nt * 4 + qn;
                float z0 = Z[mt][nt][2 * h], z1 = Z[mt][nt][2 * h + 1];
                unsigned hv;
                if (S == 1) {
                    hv = tanh_bf2(cvt_bf2u(z0, z1));
                } else {
                    __nv_bfloat162 acc = __hmul2(
                        asbf2((1 == S - 1) ? qlast[idx] : qb[rp * 68 + j2]), kc[0]);
#pragma unroll
                    for (int q = 2; q <= S - 1; q++) {
                        unsigned uq = (q == S - 1) ? qlast[idx]
                                                   : qb[(q - 1) * 4352 + rp * 68 + j2];
                        acc = __hfma2(asbf2(uq), kc[q - 1], acc);
                    }
                    unsigned au = *reinterpret_cast<unsigned*>(&acc);
                    hv = tanh_bf2(cvt_bf2u(fmaf(dt, lo16f(au), z0),
                                           fmaf(dt, hi16f(au), z1)));
                }
                *(unsigned*)&Hp[m0 + rp][hn0 + nt * 8 + qn * 2] = hv;
            }
}

__global__ void __launch_bounds__(256, 1)
ode_kernel(const float* __restrict__ t, const float* __restrict__ x,
           const float* __restrict__ W1, const float* __restrict__ b1,
           const float* __restrict__ W2, const float* __restrict__ b2,
           float* __restrict__ out) {
    extern __shared__ unsigned char raw[];
    // smem: H0 | H1 | WF(256 rows) | QB(5 tiles) | BF(256 f) | B1S(128 f)
    Row* Hbuf[2] = { (Row*)raw, (Row*)(raw + HT) };
    Row* WF = (Row*)(raw + 2 * HT);                    // [k|Q] weights, 256 rows
    unsigned* QB = (unsigned*)(raw + 104448);          // 5 * 4352 u32
    float* BF  = (float*)(raw + 191488);               // b2 | bQ
    float* B1S = (float*)(raw + 192512);               // b1
    Row* W1s = (Row*)(raw + 104448);                   // init staging (in QB)

    const int tid  = threadIdx.x;
    const int row0 = blockIdx.x * 64;
    const int lane = tid & 31, warp = tid >> 5;
    const int mg   = warp >> 2;                 // m-group 0/1
    const int slot = (warp + 2 * mg) & 3;       // 0-1: k-warps, 2-3: Q-warps
    const bool isK = slot < 2;
    const int m0  = mg * 32;
    const int wn0 = slot * 64;                  // fused out-col base
    const int hn0 = (slot - 2) * 64;            // Q-warp hidden-col base
    const int gm = lane >> 2, qn = lane & 3;
    const int lrow = lane & 15, lcol = (lane >> 4) * 8;
    const int barid = 1 + mg;
#define BARG() asm volatile("bar.sync %0, 128;" :: "r"(barid) : "memory")

    // ---- staging ----
    for (int idx = tid; idx < 128 * 128; idx += 256) {
        int k = idx >> 7, n = idx & 127;
        WF[n][k]       = __float2bfloat16(W2[idx]);           // rows 0-127: W2t
        WF[128 + n][k] = __float2bfloat16(g_W21[n * 128 + k]);// rows 128-255: W21t
        W1s[n][k]      = __float2bfloat16(W1[idx]);           // init only
    }
    if (tid < 128) { BF[tid] = b2[tid]; BF[128 + tid] = g_bQ[tid]; B1S[tid] = b1[tid]; }
    for (int idx = tid; idx < 64 * 128; idx += 256) {
        float v = x[row0 * 128 + idx];
        out[row0 * 128 + idx] = v;
        Hbuf[0][idx >> 7][idx & 127] = __float2bfloat16(v);   // A for init GEMM
    }
    __syncthreads();

    const float T   = t[0] / 10.0f;   // TIMESCALE = 10
    const float dt0 = g_dt0;

    const unsigned aoff = (unsigned)(((m0 + lrow) * PADK + lcol) * 2);
    const unsigned Ab[2] = { (unsigned)__cvta_generic_to_shared(Hbuf[0]) + aoff,
                             (unsigned)__cvta_generic_to_shared(Hbuf[1]) + aoff };
    const int browoff = (lane & 7) + ((lane >> 4) << 3);
    const int bcoloff = ((lane >> 3) & 1) * 8;
    const unsigned Bb = (unsigned)__cvta_generic_to_shared(WF)
                      + (unsigned)(((wn0 + browoff) * PADK + bcoloff) * 2);
    const float* biasp = BF + wn0;
    unsigned* qb = QB + mg * 2176;    // warp-private Q slots (bf16x2)

    float yreg[2][8][4];              // k-warps: state slice (32x64)
    float Zreg[2][8][4];              // Q-warps: Z slice
    unsigned qlast[32];               // Q-warps: latest Q packed
    float c[2][8][4];

    if (isK) {
        const float* xr = x + row0 * 128;
#pragma unroll
        for (int mt = 0; mt < 2; mt++)
#pragma unroll
            for (int nt = 0; nt < 8; nt++)
#pragma unroll
                for (int h = 0; h < 2; h++) {
                    const int r = m0 + mt * 16 + gm + 8 * h;
                    const int n = wn0 + nt * 8 + qn * 2;
                    float2 v = *(const float2*)&xr[r * 128 + n];
                    yreg[mt][nt][2 * h]     = v.x;
                    yreg[mt][nt][2 * h + 1] = v.y;
                }
    } else {
        // init: Z = x @ W1 + b1 (A = x in Hbuf[0], B = W1t staged in QB region)
        const unsigned w1b = (unsigned)__cvta_generic_to_shared(W1s)
                           + (unsigned)(((hn0 + browoff) * PADK + bcoloff) * 2);
        gemmF(Zreg, Ab[0], w1b, B1S + hn0, qn);
    }

    const __nv_bfloat162 C2b[1] = { __float2bfloat162_rn(1.f / 5.f) };
    const __nv_bfloat162 C3b[2] = { __float2bfloat162_rn(3.f / 40.f),
                                    __float2bfloat162_rn(9.f / 40.f) };
    const __nv_bfloat162 C4b[3] = { __float2bfloat162_rn(44.f / 45.f),
                                    __float2bfloat162_rn(-56.f / 15.f),
                                    __float2bfloat162_rn(32.f / 9.f) };
    const __nv_bfloat162 C5b[4] = { __float2bfloat162_rn(19372.f / 6561.f),
                                    __float2bfloat162_rn(-25360.f / 2187.f),
                                    __float2bfloat162_rn(64448.f / 6561.f),
                                    __float2bfloat162_rn(-212.f / 729.f) };
    const __nv_bfloat162 C6b[5] = { __float2bfloat162_rn(9017.f / 3168.f),
                                    __float2bfloat162_rn(-355.f / 33.f),
                                    __float2bfloat162_rn(46732.f / 5247.f),
                                    __float2bfloat162_rn(49.f / 176.f),
                                    __float2bfloat162_rn(-5103.f / 18656.f) };
    const float B1c = 35.f / 384.f, B3c = 500.f / 1113.f, B4c = 125.f / 192.f,
                B5c = -2187.f / 6784.f, B6c = 11.f / 84.f;

    // skew: m-group 1 burns one dummy GEMM so the groups' Hc/GEMM phases
    // anti-align on the SMSPs (each SMSP hosts k of one group + Q of other).
    if (mg == 1) gemmF(c, Ab[0], Bb, biasp, qn);

    float tt = 0.f;
    int p = 0;
    for (int it = 0; it < 48; it++) {
        float dt = fminf(fmaxf(T - tt, 0.f), dt0);
        if (!(dt > 0.f)) break;

#define STAGE(S, KC, BS, QI)                                                 \
        if (!isK) hc<S>(Hbuf[p], Zreg, qlast, qb, dt, KC, m0, hn0, gm, qn);  \
        BARG();                                                              \
        gemmF(c, Ab[p], Bb, biasp, qn);                                      \
        if (isK) {                                                           \
            if ((BS) != 0.f) {                                               \
                const float s_ = dt * (BS);                                  \
                _Pragma("unroll") for (int mt = 0; mt < 2; mt++)             \
                _Pragma("unroll") for (int nt = 0; nt < 8; nt++)             \
                _Pragma("unroll") for (int i = 0; i < 4; i++)                \
                    yreg[mt][nt][i] = fmaf(s_, c[mt][nt][i], yreg[mt][nt][i]);\
            }                                                                \
        } else if ((QI) >= 0) {                                              \
            _Pragma("unroll") for (int mt = 0; mt < 2; mt++)                 \
            _Pragma("unroll") for (int nt = 0; nt < 8; nt++)                 \
            _Pragma("unroll") for (int h = 0; h < 2; h++) {                  \
                const int idx = (mt * 8 + nt) * 2 + h;                       \
                const int rp = mt * 16 + gm + 8 * h;                         \
                const int j2 = (hn0 >> 1) + nt * 4 + qn;                     \
                unsigned v = cvt_bf2u(c[mt][nt][2*h], c[mt][nt][2*h+1]);     \
                qlast[idx] = v;                                              \
                qb[(QI) * 4352 + rp * 68 + j2] = v;                          \
            }                                                                \
        } else {                                                             \
            _Pragma("unroll") for (int mt = 0; mt < 2; mt++)                 \
            _Pragma("unroll") for (int nt = 0; nt < 8; nt++)                 \
            _Pragma("unroll") for (int h = 0; h < 2; h++) {                  \
                const int rp = mt * 16 + gm + 8 * h;                         \
                const int j2 = (hn0 >> 1) + nt * 4 + qn;                     \
                unsigned q1 = qb[rp * 68 + j2];                              \
                unsigned q3 = qb[2 * 4352 + rp * 68 + j2];                   \
                unsigned q4 = qb[3 * 4352 + rp * 68 + j2];                   \
                unsigned q5 = qb[4 * 4352 + rp * 68 + j2];                   \
                float u0 = fmaf(B1c, lo16f(q1), fmaf(B3c, lo16f(q3),         \
                           fmaf(B4c, lo16f(q4), fmaf(B5c, lo16f(q5),         \
                                B6c * c[mt][nt][2*h]))));                    \
                float u1 = fmaf(B1c, hi16f(q1), fmaf(B3c, hi16f(q3),         \
                           fmaf(B4c, hi16f(q4), fmaf(B5c, hi16f(q5),         \
                                B6c * c[mt][nt][2*h+1]))));                  \
                Zreg[mt][nt][2*h]   = fmaf(dt, u0, Zreg[mt][nt][2*h]);       \
                Zreg[mt][nt][2*h+1] = fmaf(dt, u1, Zreg[mt][nt][2*h+1]);     \
            }                                                                \
        }                                                                    \
        p ^= 1;

        STAGE(1, C2b, B1c, 0)
        STAGE(2, C2b, 0.f, 1)
        STAGE(3, C3b, B3c, 2)
        STAGE(4, C4b, B4c, 3)
        STAGE(5, C5b, B5c, 4)
        STAGE(6, C6b, B6c, -1)
#undef STAGE
        tt += dt;
    }

    // ---- out[1] = yT (k-warps hold the state) ----
    if (isK) {
        float* o1 = out + 8192 * 128 + row0 * 128;
#pragma unroll
        for (int mt = 0; mt < 2; mt++)
#pragma unroll
            for (int nt = 0; nt < 8; nt++)
#pragma unroll
                for (int h = 0; h < 2; h++) {
                    const int r = m0 + mt * 16 + gm + 8 * h;
                    const int n = wn0 + nt * 8 + qn * 2;
                    float2 v;
                    v.x = yreg[mt][nt][2 * h];
                    v.y = yreg[mt][nt][2 * h + 1];
                    *(float2*)&o1[r * 128 + n] = v;
                }
    }
#undef BARG
}

// ---- prep: W21 (fp32, [n][hid]) and bQ = b2@W1 ----
__global__ void w21_kernel(const float* __restrict__ W1, const float* __restrict__ W2,
                           const float* __restrict__ b2) {
    __shared__ float w2r[128];
    int n = threadIdx.x;
    if (blockIdx.x == 128) {
        float acc = 0.f;
        for (int d = 0; d < 128; d++) acc = fmaf(b2[d], W1[d * 128 + n], acc);
        g_bQ[n] = acc;
        return;
    }
    int hk = blockIdx.x;
    w2r[n] = W2[hk * 128 + n];
    __syncthreads();
    float acc = 0.f;
    for (int d = 0; d < 128; d++) acc = fmaf(w2r[d], W1[d * 128 + n], acc);
    g_W21[n * 128 + hk] = acc;
}

// ---- dt0: faithful fp32 initial_step_size on x[0] (proven) ----
__device__ __forceinline__ float bsum(float v, float* buf, int j) {
    buf[j] = v; __syncthreads();
    for (int s = 64; s > 0; s >>= 1) { if (j < s) buf[j] += buf[j + s]; __syncthreads(); }
    float r = buf[0]; __syncthreads(); return r;
}
__device__ __forceinline__ void mlp128(const float* yin, float* fout, float* hid,
                                       const float* W1, const float* b1,
                                       const float* W2, const float* b2, int j) {
    float acc = 0.f;
    for (int i = 0; i < 128; i++) acc += yin[i] * W1[i * 128 + j];
    hid[j] = tanhf(acc + b1[j]);
    __syncthreads();
    acc = 0.f;
    for (int i = 0; i < 128; i++) acc += hid[i] * W2[i * 128 + j];
    fout[j] = acc + b2[j];
    __syncthreads();
}
__global__ void dt0_kernel(const float* __restrict__ t, const float* __restrict__ x,
                           const float* __restrict__ W1, const float* __restrict__ b1,
                           const float* __restrict__ W2, const float* __restrict__ b2) {
    __shared__ float y0[128], f0v[128], f1v[128], y1s[128], hid[128], buf[128];
    int j = threadIdx.x;
    y0[j] = x[j];
    __syncthreads();
    mlp128(y0, f0v, hid, W1, b1, W2, b2, j);
    float scale = 1.4e-8f + fabsf(y0[j]) * 1.4e-8f;
    float a0 = y0[j] / scale;
    float d0 = sqrtf(bsum(a0 * a0, buf, j));
    float a1 = f0v[j] / scale;
    float d1 = sqrtf(bsum(a1 * a1, buf, j));
    float h0 = (d0 < 1e-5f || d1 < 1e-5f) ? 1e-6f : (0.01f * d0) / d1;
    y1s[j] = y0[j] + h0 * f0v[j];
    __syncthreads();
    mlp128(y1s, f1v, hid, W1, b1, W2, b2, j);
    float a2 = (f1v[j] - f0v[j]) / scale;
    float d2 = sqrtf(bsum(a2 * a2, buf, j)) / h0;
    float h1 = (d1 <= 1e-15f && d2 <= 1e-15f) ? fmaxf(1e-6f, h0 * 1e-3f)
                                              : powf(0.01f / (d1 + d2), 0.2f);
    if (j == 0) g_dt0 = fminf(100.0f * h0, h1);
}

extern "C" void kernel_launch(void* const* d_in, const int* in_sizes, int n_in,
                              void* d_out, int out_size) {
    const float* t  = (const float*)d_in[0];
    const float* x  = (const float*)d_in[1];
    const float* W1 = (const float*)d_in[2];
    const float* b1 = (const float*)d_in[3];
    const float* W2 = (const float*)d_in[4];
    const float* b2 = (const float*)d_in[5];
    float* out = (float*)d_out;

    w21_kernel<<<129, 128>>>(W1, W2, b2);
    dt0_kernel<<<1, 128>>>(t, x, W1, b1, W2, b2);

    int smem = 193024;   // H0|H1|WF|QB|BF|B1S
    cudaFuncSetAttribute(ode_kernel, cudaFuncAttributeMaxDynamicSharedMemorySize, smem);
    ode_kernel<<<128, 256, smem>>>(t, x, W1, b1, W2, b2, out);
}

// round 15
// speedup vs baseline: 1.4645x; 1.4645x over previous
#include <cuda_runtime.h>
#include <cuda_bf16.h>

// ---------------------------------------------------------------------------
// NeuralODE Dopri5, R15: R13 data layout + explicit dual-stream software
// pipeline. Each m-group's 32 rows = two independent 16-row streams offset by
// two phases; every phase = one GEMM (one stream) + one elementwise chunk
// (other stream) + one 128-thread barrier, so the tensor pipe is fed in every
// phase instead of idling through elementwise/barrier windows (tensor was
// pinned at ~45% for 9 rounds).
// ---------------------------------------------------------------------------

#define PADK 136                       // bf16 row stride (272 B): conflict-free
#define TB   (64 * PADK * 2)           // one 64x128(+pad) bf16 tile = 17408 B
typedef __nv_bfloat16 Row[PADK];

__device__ float g_dt0;

__device__ __forceinline__ unsigned cvt_bf2u(float lo, float hi) {
    unsigned r; asm("cvt.rn.bf16x2.f32 %0, %1, %2;" : "=r"(r) : "f"(hi), "f"(lo)); return r;
}
__device__ __forceinline__ unsigned tanh_bf2(unsigned p) {
    unsigned r; asm("tanh.approx.bf16x2 %0, %1;" : "=r"(r) : "r"(p)); return r;
}
__device__ __forceinline__ float lo16f(unsigned u) { return __uint_as_float(u << 16); }
__device__ __forceinline__ float hi16f(unsigned u) { return __uint_as_float(u & 0xFFFF0000u); }
__device__ __forceinline__ __nv_bfloat162 asbf2(unsigned u) {
    return *reinterpret_cast<__nv_bfloat162*>(&u);
}
__device__ __forceinline__ void mma_bf16(float* c, const unsigned* a, const unsigned* b) {
    asm volatile("mma.sync.aligned.m16n8k16.row.col.f32.bf16.bf16.f32 "
                 "{%0,%1,%2,%3}, {%4,%5,%6,%7}, {%8,%9}, {%0,%1,%2,%3};"
                 : "+f"(c[0]), "+f"(c[1]), "+f"(c[2]), "+f"(c[3])
                 : "r"(a[0]), "r"(a[1]), "r"(a[2]), "r"(a[3]), "r"(b[0]), "r"(b[1]));
}
__device__ __forceinline__ void ldsm_x4(unsigned a[4], unsigned addr) {
    asm volatile("ldmatrix.sync.aligned.m8n8.x4.shared.b16 {%0,%1,%2,%3}, [%4];"
                 : "=r"(a[0]), "=r"(a[1]), "=r"(a[2]), "=r"(a[3]) : "r"(addr));
}

// GEMM1 (16-row stream tile): C[16x32] = A[16x128] @ W1t^T + b1. B from regs.
__device__ __forceinline__ void gemm1h(float c[4][4], unsigned abase,
                                       const unsigned (&wb)[4][8][2],
                                       const float* bias, int n0, int qn) {
#pragma unroll
    for (int nt = 0; nt < 4; nt++) {
        const int nb = n0 + nt * 8 + qn * 2;
        c[nt][0] = c[nt][2] = bias[nb];
        c[nt][1] = c[nt][3] = bias[nb + 1];
    }
#pragma unroll
    for (int kk = 0; kk < 8; kk++) {
        unsigned a[4];
        ldsm_x4(a, abase + kk * 32);
#pragma unroll
        for (int nt = 0; nt < 4; nt++)
            mma_bf16(c[nt], a, wb[nt][kk]);
    }
}

// GEMM2 (16-row stream tile): C = H @ W2t^T + b2. B via ldmatrix.
__device__ __forceinline__ void gemm2h(float c[4][4], unsigned abase,
                                       unsigned bw0, unsigned bw1,
                                       const float* bias, int n0, int qn) {
#pragma unroll
    for (int nt = 0; nt < 4; nt++) {
        const int nb = n0 + nt * 8 + qn * 2;
        c[nt][0] = c[nt][2] = bias[nb];
        c[nt][1] = c[nt][3] = bias[nb + 1];
    }
#pragma unroll
    for (int kk = 0; kk < 8; kk++) {
        unsigned a[4], b0[4], b1[4];
        ldsm_x4(a, abase + kk * 32);
        ldsm_x4(b0, bw0 + kk * 32);
        ldsm_x4(b1, bw1 + kk * 32);
        mma_bf16(c[0], a, b0);
        mma_bf16(c[1], a, b0 + 2);
        mma_bf16(c[2], a, b1);
        mma_bf16(c[3], a, b1 + 2);
    }
}

// Stage arg for a 16-row stream: Abuf rows rb..rb+16 = bf16(y + dt*combo(kp)).
template <int NK>
__device__ __forceinline__ void build_arg16(Row* Abuf, const unsigned (&kp)[5][8],
                                            const float (&y)[4][4],
                                            float dt, const __nv_bfloat162* kc,
                                            int rb, int n0, int gm, int qn) {
#pragma unroll
    for (int nt = 0; nt < 4; nt++)
#pragma unroll
        for (int h = 0; h < 2; h++) {
            const int id = nt * 2 + h;
            const int r = rb + gm + 8 * h;
            const int n = n0 + nt * 8 + qn * 2;
            unsigned v;
            if (NK == 0) {
                v = cvt_bf2u(y[nt][2 * h], y[nt][2 * h + 1]);
            } else {
                __nv_bfloat162 acc = __hmul2(asbf2(kp[0][id]), kc[0]);
#pragma unroll
                for (int q = 1; q < NK; q++)
                    acc = __hfma2(asbf2(kp[q][id]), kc[q], acc);
                unsigned au = *reinterpret_cast<unsigned*>(&acc);
                v = cvt_bf2u(fmaf(dt, lo16f(au), y[nt][2 * h]),
                             fmaf(dt, hi16f(au), y[nt][2 * h + 1]));
            }
            *(unsigned*)&Abuf[r][n] = v;
        }
}

__device__ __forceinline__ void storeh16(Row* dst, const float c[4][4],
                                         int rb, int n0, int gm, int qn) {
#pragma unroll
    for (int nt = 0; nt < 4; nt++) {
        const int r = rb + gm;
        const int n = n0 + nt * 8 + qn * 2;
        *(unsigned*)&dst[r][n]     = tanh_bf2(cvt_bf2u(c[nt][0], c[nt][1]));
        *(unsigned*)&dst[r + 8][n] = tanh_bf2(cvt_bf2u(c[nt][2], c[nt][3]));
    }
}

__global__ void __launch_bounds__(256, 1)
ode_kernel(const float* __restrict__ t, const float* __restrict__ x,
           const float* __restrict__ W1, const float* __restrict__ b1,
           const float* __restrict__ W2, const float* __restrict__ b2,
           float* __restrict__ out) {
    extern __shared__ unsigned char raw[];
    Row* Abufs[2] = { (Row*)(raw + 0 * TB), (Row*)(raw + 1 * TB) };
    Row* Hbufs[2] = { (Row*)(raw + 2 * TB), (Row*)(raw + 3 * TB) };
    Row* Wst2 = (Row*)(raw + 4 * TB);
    float* bstag = (float*)(raw + 4 * TB + 128 * PADK * 2);
    Row* Wst = (Row*)raw;                 // W1 staging (dead after init)

    const int tid  = threadIdx.x;
    const int row0 = blockIdx.x * 64;
    const int lane = tid & 31, warp = tid >> 5;
    const int m0 = (warp & 1) * 32;       // m-group (R13 mapping)
    const int n0 = (warp >> 1) * 32;
    const int gm = lane >> 2, qn = lane & 3;
    const int barid = 1 + (warp & 1);
    const int lrow = lane & 15, lcol = (lane >> 4) * 8;
    const int rbA = m0, rbB = m0 + 16;    // stream row bases

#define PH_BAR asm volatile("bar.sync %0, 128;" :: "r"(barid) : "memory")

    // ---- staging ----
    for (int idx = tid; idx < 128 * 128; idx += 256) {
        int k = idx >> 7, n = idx & 127;
        Wst[n][k]  = __float2bfloat16(W1[idx]);
        Wst2[n][k] = __float2bfloat16(W2[idx]);
    }
    if (tid < 128) { bstag[tid] = b1[tid]; bstag[128 + tid] = b2[tid]; }
    for (int idx = tid; idx < 64 * 128; idx += 256)
        out[row0 * 128 + idx] = x[row0 * 128 + idx];
    __syncthreads();

    // ---- W1 B-fragments -> registers ----
    unsigned wb1[4][8][2];
#pragma unroll
    for (int nt = 0; nt < 4; nt++) {
        const int n = n0 + nt * 8 + gm;
#pragma unroll
        for (int kk = 0; kk < 8; kk++) {
            const int kb = kk * 16 + qn * 2;
            wb1[nt][kk][0] = *(const unsigned*)&Wst[n][kb];
            wb1[nt][kk][1] = *(const unsigned*)&Wst[n][kb + 8];
        }
    }

    // ---- state y -> registers, per stream ----
    float yA[4][4], yB[4][4];
    {
        const float* xr = x + row0 * 128;
#pragma unroll
        for (int nt = 0; nt < 4; nt++)
#pragma unroll
            for (int h = 0; h < 2; h++) {
                const int n = n0 + nt * 8 + qn * 2;
                float2 vA = *(const float2*)&xr[(rbA + gm + 8 * h) * 128 + n];
                float2 vB = *(const float2*)&xr[(rbB + gm + 8 * h) * 128 + n];
                yA[nt][2 * h] = vA.x; yA[nt][2 * h + 1] = vA.y;
                yB[nt][2 * h] = vB.x; yB[nt][2 * h + 1] = vB.y;
            }
    }
    __syncthreads();   // staging dead

    const float T   = t[0] / 10.0f;    // TIMESCALE = 10
    const float dt0 = g_dt0;

    const unsigned aoffA = (unsigned)(((rbA + lrow) * PADK + lcol) * 2);
    const unsigned aoffB = (unsigned)(((rbB + lrow) * PADK + lcol) * 2);
    const unsigned AbA[2] = { (unsigned)__cvta_generic_to_shared(Abufs[0]) + aoffA,
                              (unsigned)__cvta_generic_to_shared(Abufs[1]) + aoffA };
    const unsigned AbB[2] = { (unsigned)__cvta_generic_to_shared(Abufs[0]) + aoffB,
                              (unsigned)__cvta_generic_to_shared(Abufs[1]) + aoffB };
    const unsigned HbA[2] = { (unsigned)__cvta_generic_to_shared(Hbufs[0]) + aoffA,
                              (unsigned)__cvta_generic_to_shared(Hbufs[1]) + aoffA };
    const unsigned HbB[2] = { (unsigned)__cvta_generic_to_shared(Hbufs[0]) + aoffB,
                              (unsigned)__cvta_generic_to_shared(Hbufs[1]) + aoffB };
    const int browoff = (lane & 7) + ((lane >> 4) << 3);
    const int bcoloff = ((lane >> 3) & 1) * 8;
    const unsigned Bw0 = (unsigned)__cvta_generic_to_shared(Wst2)
                       + (unsigned)(((n0 + browoff) * PADK + bcoloff) * 2);
    const unsigned Bw1 = Bw0 + 16 * PADK * 2;
    const float* bias1 = bstag;
    const float* bias2 = bstag + 128;

    const __nv_bfloat162 C2b[1] = { __float2bfloat162_rn(1.f / 5.f) };
    const __nv_bfloat162 C3b[2] = { __float2bfloat162_rn(3.f / 40.f),
                                    __float2bfloat162_rn(9.f / 40.f) };
    const __nv_bfloat162 C4b[3] = { __float2bfloat162_rn(44.f / 45.f),
                                    __float2bfloat162_rn(-56.f / 15.f),
                                    __float2bfloat162_rn(32.f / 9.f) };
    const __nv_bfloat162 C5b[4] = { __float2bfloat162_rn(19372.f / 6561.f),
                                    __float2bfloat162_rn(-25360.f / 2187.f),
                                    __float2bfloat162_rn(64448.f / 6561.f),
                                    __float2bfloat162_rn(-212.f / 729.f) };
    const __nv_bfloat162 C6b[5] = { __float2bfloat162_rn(9017.f / 3168.f),
                                    __float2bfloat162_rn(-355.f / 33.f),
                                    __float2bfloat162_rn(46732.f / 5247.f),
                                    __float2bfloat162_rn(49.f / 176.f),
                                    __float2bfloat162_rn(-5103.f / 18656.f) };
    const float B1c = 35.f / 384.f, B3c = 500.f / 1113.f, B4c = 125.f / 192.f,
                B5c = -2187.f / 6784.f, B6c = 11.f / 84.f;

#define KPST(kp, q, c)                                                       \
    _Pragma("unroll") for (int nt = 0; nt < 4; nt++)                         \
    _Pragma("unroll") for (int h = 0; h < 2; h++)                            \
        kp[q][nt * 2 + h] = cvt_bf2u(c[nt][2 * h], c[nt][2 * h + 1]);

#define YUPD(y, kp, c, dtv)                                                  \
    _Pragma("unroll") for (int nt = 0; nt < 4; nt++)                         \
    _Pragma("unroll") for (int h = 0; h < 2; h++) {                          \
        const int id = nt * 2 + h;                                           \
        float u0 = fmaf(B1c, lo16f(kp[0][id]), fmaf(B3c, lo16f(kp[2][id]),   \
                   fmaf(B4c, lo16f(kp[3][id]), fmaf(B5c, lo16f(kp[4][id]),   \
                        B6c * c[nt][2 * h]))));                              \
        float u1 = fmaf(B1c, hi16f(kp[0][id]), fmaf(B3c, hi16f(kp[2][id]),   \
                   fmaf(B4c, hi16f(kp[3][id]), fmaf(B5c, hi16f(kp[4][id]),   \
                        B6c * c[nt][2 * h + 1]))));                          \
        y[nt][2 * h]     = fmaf(dtv, u0, y[nt][2 * h]);                      \
        y[nt][2 * h + 1] = fmaf(dtv, u1, y[nt][2 * h + 1]);                  \
    }

    unsigned kpA[5][8], kpB[5][8];
    float cA[4][4], cB[4][4];
    float dtA = 0.f, dtB = 0.f;
    int pA = 0, pB = 0;
    int nsteps = 0;
    float tt = 0.f;

    // stage s >= 2 (B's phi0 finishes B stage s-1 with kp index QPREV = s-2)
#define STG(NK, KC, QA, QPREV)                                               \
    /* phi0 */                                                               \
    gemm2h(cB, HbB[pB], Bw0, Bw1, bias2, n0, qn);                            \
    KPST(kpB, QPREV, cB);                                                    \
    pB ^= 1;                                                                 \
    build_arg16<NK>(Abufs[pA], kpA, yA, dtA, KC, rbA, n0, gm, qn);           \
    PH_BAR;                                                                  \
    /* phi1 */                                                               \
    gemm1h(cA, AbA[pA], wb1, bias1, n0, qn);                                 \
    build_arg16<NK>(Abufs[pB], kpB, yB, dtB, KC, rbB, n0, gm, qn);           \
    PH_BAR;                                                                  \
    /* phi2 */                                                               \
    gemm1h(cB, AbB[pB], wb1, bias1, n0, qn);                                 \
    storeh16(Hbufs[pA], cA, rbA, n0, gm, qn);                                \
    PH_BAR;                                                                  \
    /* phi3 */                                                               \
    gemm2h(cA, HbA[pA], Bw0, Bw1, bias2, n0, qn);                            \
    if ((QA) >= 0) { KPST(kpA, QA, cA); } else { YUPD(yA, kpA, cA, dtA); }   \
    pA ^= 1;                                                                 \
    storeh16(Hbufs[pB], cB, rbB, n0, gm, qn);                                \
    PH_BAR;

    for (int it = 0; it < 48; it++) {
        float dt = fminf(fmaxf(T - tt, 0.f), dt0);
        if (!(dt > 0.f)) break;
        dtA = dt;
        nsteps++;

        // ---- stage 1 (B's phi0 finishes B stage 6 of previous step) ----
        if (it > 0) {
            gemm2h(cB, HbB[pB], Bw0, Bw1, bias2, n0, qn);
            YUPD(yB, kpB, cB, dtB);
            pB ^= 1;
        }
        dtB = dtA;
        build_arg16<0>(Abufs[pA], kpA, yA, dtA, C2b, rbA, n0, gm, qn);
        PH_BAR;
        gemm1h(cA, AbA[pA], wb1, bias1, n0, qn);
        build_arg16<0>(Abufs[pB], kpB, yB, dtB, C2b, rbB, n0, gm, qn);
        PH_BAR;
        gemm1h(cB, AbB[pB], wb1, bias1, n0, qn);
        storeh16(Hbufs[pA], cA, rbA, n0, gm, qn);
        PH_BAR;
        gemm2h(cA, HbA[pA], Bw0, Bw1, bias2, n0, qn);
        KPST(kpA, 0, cA);
        pA ^= 1;
        storeh16(Hbufs[pB], cB, rbB, n0, gm, qn);
        PH_BAR;

        // ---- stages 2..6 ----
        STG(1, C2b, 1, 0)     // A stage2 -> kp1 ; B finishes stage1 -> kp0
        STG(2, C3b, 2, 1)     // A stage3 ; B stage2
        STG(3, C4b, 3, 2)     // A stage4 ; B stage3
        STG(4, C5b, 4, 3)     // A stage5 ; B stage4
        STG(5, C6b, -1, 4)    // A stage6 (y-update) ; B stage5
        tt += dt;
    }
#undef STG

    // ---- epilogue: B still owes stage-6 GEMM2 + y-update for last step ----
    if (nsteps > 0) {
        gemm2h(cB, HbB[pB], Bw0, Bw1, bias2, n0, qn);
        YUPD(yB, kpB, cB, dtB);
    }

    // ---- out[1] = yT (both streams) ----
    float* o1 = out + 8192 * 128 + row0 * 128;
#pragma unroll
    for (int nt = 0; nt < 4; nt++)
#pragma unroll
        for (int h = 0; h < 2; h++) {
            const int n = n0 + nt * 8 + qn * 2;
            float2 vA, vB;
            vA.x = yA[nt][2 * h]; vA.y = yA[nt][2 * h + 1];
            vB.x = yB[nt][2 * h]; vB.y = yB[nt][2 * h + 1];
            *(float2*)&o1[(rbA + gm + 8 * h) * 128 + n] = vA;
            *(float2*)&o1[(rbB + gm + 8 * h) * 128 + n] = vB;
        }
#undef PH_BAR
#undef KPST
#undef YUPD
}

// ---------------------------------------------------------------------------
// dt0: faithful fp32 port of initial_step_size on x[0]. (unchanged, proven)
// ---------------------------------------------------------------------------
__device__ __forceinline__ float bsum(float v, float* buf, int j) {
    buf[j] = v; __syncthreads();
    for (int s = 64; s > 0; s >>= 1) { if (j < s) buf[j] += buf[j + s]; __syncthreads(); }
    float r = buf[0]; __syncthreads(); return r;
}
__device__ __forceinline__ void mlp128(const float* yin, float* fout, float* hid,
                                       const float* W1, const float* b1,
                                       const float* W2, const float* b2, int j) {
    float acc = 0.f;
    for (int i = 0; i < 128; i++) acc += yin[i] * W1[i * 128 + j];
    hid[j] = tanhf(acc + b1[j]);
    __syncthreads();
    acc = 0.f;
    for (int i = 0; i < 128; i++) acc += hid[i] * W2[i * 128 + j];
    fout[j] = acc + b2[j];
    __syncthreads();
}
__global__ void dt0_kernel(const float* __restrict__ t, const float* __restrict__ x,
                           const float* __restrict__ W1, const float* __restrict__ b1,
                           const float* __restrict__ W2, const float* __restrict__ b2) {
    __shared__ float y0[128], f0v[128], f1v[128], y1s[128], hid[128], buf[128];
    int j = threadIdx.x;
    y0[j] = x[j];
    __syncthreads();
    mlp128(y0, f0v, hid, W1, b1, W2, b2, j);
    float scale = 1.4e-8f + fabsf(y0[j]) * 1.4e-8f;
    float a0 = y0[j] / scale;
    float d0 = sqrtf(bsum(a0 * a0, buf, j));
    float a1 = f0v[j] / scale;
    float d1 = sqrtf(bsum(a1 * a1, buf, j));
    float h0 = (d0 < 1e-5f || d1 < 1e-5f) ? 1e-6f : (0.01f * d0) / d1;
    y1s[j] = y0[j] + h0 * f0v[j];
    __syncthreads();
    mlp128(y1s, f1v, hid, W1, b1, W2, b2, j);
    float a2 = (f1v[j] - f0v[j]) / scale;
    float d2 = sqrtf(bsum(a2 * a2, buf, j)) / h0;
    float h1 = (d1 <= 1e-15f && d2 <= 1e-15f) ? fmaxf(1e-6f, h0 * 1e-3f)
                                              : powf(0.01f / (d1 + d2), 0.2f);
    if (j == 0) g_dt0 = fminf(100.0f * h0, h1);
}

extern "C" void kernel_launch(void* const* d_in, const int* in_sizes, int n_in,
                              void* d_out, int out_size) {
    const float* t  = (const float*)d_in[0];
    const float* x  = (const float*)d_in[1];
    const float* W1 = (const float*)d_in[2];
    const float* b1 = (const float*)d_in[3];
    const float* W2 = (const float*)d_in[4];
    const float* b2 = (const float*)d_in[5];
    float* out = (float*)d_out;

    dt0_kernel<<<1, 128>>>(t, x, W1, b1, W2, b2);

    int smem = 4 * TB + 128 * PADK * 2 + 1024;   // 105472 B (as R13)
    cudaFuncSetAttribute(ode_kernel, cudaFuncAttributeMaxDynamicSharedMemorySize, smem);
    ode_kernel<<<128, 256, smem>>>(t, x, W1, b1, W2, b2, out);
}

// round 16
// speedup vs baseline: 1.5638x; 1.0678x over previous
#include <cuda_runtime.h>
#include <cuda_bf16.h>

// ---------------------------------------------------------------------------
// NeuralODE Dopri5 fused persistent kernel. R16 = R13 (best, 176.5us) with a
// compressed build_arg: arg = HFMA2(combo, bf16x2(dt), bf16x2(y)) -- one
// dependent op after the k-combo chain instead of unpack+2*FFMA+CVT (saves
// ~240 instr/step/warp and ~16 cyc of serial latency per slot). All other
// structure identical to R13 (R9 mapping, tanh_bf2, skew prologue).
// ---------------------------------------------------------------------------

#define PADK 136                       // bf16 row stride (272 B): conflict-free
#define TB   (64 * PADK * 2)           // one 64x128(+pad) bf16 tile = 17408 B
typedef __nv_bfloat16 Row[PADK];

__device__ float g_dt0;

__device__ __forceinline__ unsigned cvt_bf2u(float lo, float hi) {
    unsigned r; asm("cvt.rn.bf16x2.f32 %0, %1, %2;" : "=r"(r) : "f"(hi), "f"(lo)); return r;
}
__device__ __forceinline__ unsigned tanh_bf2(unsigned p) {
    unsigned r; asm("tanh.approx.bf16x2 %0, %1;" : "=r"(r) : "r"(p)); return r;
}
__device__ __forceinline__ float lo16f(unsigned u) { return __uint_as_float(u << 16); }
__device__ __forceinline__ float hi16f(unsigned u) { return __uint_as_float(u & 0xFFFF0000u); }
__device__ __forceinline__ __nv_bfloat162 asbf2(unsigned u) {
    return *reinterpret_cast<__nv_bfloat162*>(&u);
}
__device__ __forceinline__ unsigned hfma2u(unsigned a, unsigned b, unsigned c) {
    __nv_bfloat162 r = __hfma2(asbf2(a), asbf2(b), asbf2(c));
    return *reinterpret_cast<unsigned*>(&r);
}
__device__ __forceinline__ void mma_bf16(float* c, const unsigned* a, const unsigned* b) {
    asm volatile("mma.sync.aligned.m16n8k16.row.col.f32.bf16.bf16.f32 "
                 "{%0,%1,%2,%3}, {%4,%5,%6,%7}, {%8,%9}, {%0,%1,%2,%3};"
                 : "+f"(c[0]), "+f"(c[1]), "+f"(c[2]), "+f"(c[3])
                 : "r"(a[0]), "r"(a[1]), "r"(a[2]), "r"(a[3]), "r"(b[0]), "r"(b[1]));
}
__device__ __forceinline__ void ldsm_x4(unsigned a[4], unsigned addr) {
    asm volatile("ldmatrix.sync.aligned.m8n8.x4.shared.b16 {%0,%1,%2,%3}, [%4];"
                 : "=r"(a[0]), "=r"(a[1]), "=r"(a[2]), "=r"(a[3]) : "r"(addr));
}

// GEMM1: C[32x32] = A[32x128] @ W1t^T + b1. B from registers, bias from smem.
__device__ __forceinline__ void gemm_w1(float c[2][4][4], unsigned abase,
                                        const unsigned (&wb)[4][8][2],
                                        const float* bias, int n0, int qn) {
#pragma unroll
    for (int nt = 0; nt < 4; nt++) {
        const int nb = n0 + nt * 8 + qn * 2;
        float b0 = bias[nb], b1v = bias[nb + 1];
#pragma unroll
        for (int mt = 0; mt < 2; mt++) {
            c[mt][nt][0] = c[mt][nt][2] = b0;
            c[mt][nt][1] = c[mt][nt][3] = b1v;
        }
    }
#pragma unroll
    for (int kk = 0; kk < 8; kk++) {
        unsigned a[2][4];
#pragma unroll
        for (int mt = 0; mt < 2; mt++)
            ldsm_x4(a[mt], abase + mt * (16 * PADK * 2) + kk * 32);
#pragma unroll
        for (int mt = 0; mt < 2; mt++)
#pragma unroll
            for (int nt = 0; nt < 4; nt++)
                mma_bf16(c[mt][nt], a[mt], wb[nt][kk]);
    }
}

// GEMM2: C = H @ W2t^T + b2. B via two ldmatrix.x4 per kk, bias from smem.
__device__ __forceinline__ void gemm_w2(float c[2][4][4], unsigned abase,
                                        unsigned bw0, unsigned bw1,
                                        const float* bias, int n0, int qn) {
#pragma unroll
    for (int nt = 0; nt < 4; nt++) {
        const int nb = n0 + nt * 8 + qn * 2;
        float b0 = bias[nb], b1v = bias[nb + 1];
#pragma unroll
        for (int mt = 0; mt < 2; mt++) {
            c[mt][nt][0] = c[mt][nt][2] = b0;
            c[mt][nt][1] = c[mt][nt][3] = b1v;
        }
    }
#pragma unroll
    for (int kk = 0; kk < 8; kk++) {
        unsigned a[2][4], b0[4], b1[4];
#pragma unroll
        for (int mt = 0; mt < 2; mt++)
            ldsm_x4(a[mt], abase + mt * (16 * PADK * 2) + kk * 32);
        ldsm_x4(b0, bw0 + kk * 32);
        ldsm_x4(b1, bw1 + kk * 32);
#pragma unroll
        for (int mt = 0; mt < 2; mt++) {
            mma_bf16(c[mt][0], a[mt], b0);
            mma_bf16(c[mt][1], a[mt], b0 + 2);
            mma_bf16(c[mt][2], a[mt], b1);
            mma_bf16(c[mt][3], a[mt], b1 + 2);
        }
    }
}

// R16 stage arg: Abuf = HFMA2(combo(kp), bf16x2(dt), bf16x2(y)).
// yb-cvt is independent of the combo chain (issues in parallel); exactly one
// dependent op (HFMA2) follows the combo before the STS.
template <int NK>
__device__ __forceinline__ void build_arg(Row* Abuf, const unsigned (&kp)[5][16],
                                          const float (&y)[2][4][4],
                                          unsigned dtb, const __nv_bfloat162* kc,
                                          int m0, int n0, int gm, int qn) {
#pragma unroll
    for (int mt = 0; mt < 2; mt++)
#pragma unroll
        for (int nt = 0; nt < 4; nt++)
#pragma unroll
            for (int h = 0; h < 2; h++) {
                const int id = (mt * 4 + nt) * 2 + h;
                const int r = m0 + mt * 16 + gm + 8 * h;
                const int n = n0 + nt * 8 + qn * 2;
                unsigned yb = cvt_bf2u(y[mt][nt][2 * h], y[mt][nt][2 * h + 1]);
                unsigned v;
                if (NK == 0) {
                    v = yb;
                } else {
                    __nv_bfloat162 acc = __hmul2(asbf2(kp[0][id]), kc[0]);
#pragma unroll
                    for (int q = 1; q < NK; q++)
                        acc = __hfma2(asbf2(kp[q][id]), kc[q], acc);
                    v = hfma2u(*reinterpret_cast<unsigned*>(&acc), dtb, yb);
                }
                *(unsigned*)&Abuf[r][n] = v;
            }
}

// pack first, ONE tanh.approx.bf16x2 per pair.
__device__ __forceinline__ void store_h(Row* dst, const float c[2][4][4],
                                        int m0, int n0, int gm, int qn) {
#pragma unroll
    for (int mt = 0; mt < 2; mt++)
#pragma unroll
        for (int nt = 0; nt < 4; nt++) {
            const int r = m0 + mt * 16 + gm;
            const int n = n0 + nt * 8 + qn * 2;
            *(unsigned*)&dst[r][n] =
                tanh_bf2(cvt_bf2u(c[mt][nt][0], c[mt][nt][1]));
            *(unsigned*)&dst[r + 8][n] =
                tanh_bf2(cvt_bf2u(c[mt][nt][2], c[mt][nt][3]));
        }
}

__global__ void __launch_bounds__(256, 1)
ode_kernel(const float* __restrict__ t, const float* __restrict__ x,
           const float* __restrict__ W1, const float* __restrict__ b1,
           const float* __restrict__ W2, const float* __restrict__ b2,
           float* __restrict__ out) {
    extern __shared__ unsigned char raw[];
    // smem: Abuf0 | Abuf1 | Hbuf0 | Hbuf1 | Wt2 | bstag
    Row* Abufs[2] = { (Row*)(raw + 0 * TB), (Row*)(raw + 1 * TB) };
    Row* Hbufs[2] = { (Row*)(raw + 2 * TB), (Row*)(raw + 3 * TB) };
    Row* Wst2 = (Row*)(raw + 4 * TB);                      // permanent
    float* bstag = (float*)(raw + 4 * TB + 128 * PADK * 2);// 256 floats
    Row* Wst = (Row*)raw;                                  // W1 staging (dead later)

    const int tid  = threadIdx.x;
    const int row0 = blockIdx.x * 64;
    const int lane = tid & 31, warp = tid >> 5;
    const int m0 = (warp & 1) * 32;        // R9/R13 mapping (best)
    const int n0 = (warp >> 1) * 32;       // 4 n-positions
    const int gm = lane >> 2;              // 0..7
    const int qn = lane & 3;               // 0..3
    const int barid = 1 + (warp & 1);      // named barrier per m-group (4 warps)
    const int lrow = lane & 15;
    const int lcol = (lane >> 4) * 8;

#define BARG() asm volatile("bar.sync %0, 128;" :: "r"(barid) : "memory")

    // ---- stage W1 (transposed) into tiles 0-1; W2 into permanent Wt2 ----
    for (int idx = tid; idx < 128 * 128; idx += 256) {
        int k = idx >> 7, n = idx & 127;
        Wst[n][k]  = __float2bfloat16(W1[idx]);
        Wst2[n][k] = __float2bfloat16(W2[idx]);
    }
    if (tid < 128) { bstag[tid] = b1[tid]; bstag[128 + tid] = b2[tid]; }
    for (int idx = tid; idx < 64 * 128; idx += 256)
        out[row0 * 128 + idx] = x[row0 * 128 + idx];
    __syncthreads();

    // ---- W1 B-fragments -> registers (64 regs) ----
    unsigned wb1[4][8][2];
#pragma unroll
    for (int nt = 0; nt < 4; nt++) {
        const int n = n0 + nt * 8 + gm;
#pragma unroll
        for (int kk = 0; kk < 8; kk++) {
            const int kb = kk * 16 + qn * 2;
            wb1[nt][kk][0] = *(const unsigned*)&Wst[n][kb];
            wb1[nt][kk][1] = *(const unsigned*)&Wst[n][kb + 8];
        }
    }

    // ---- state y -> registers (C-fragment layout) ----
    float yreg[2][4][4];
    {
        const float* xr = x + row0 * 128;
#pragma unroll
        for (int mt = 0; mt < 2; mt++)
#pragma unroll
            for (int nt = 0; nt < 4; nt++)
#pragma unroll
                for (int h = 0; h < 2; h++) {
                    const int r = m0 + mt * 16 + gm + 8 * h;
                    const int n = n0 + nt * 8 + qn * 2;
                    float2 v = *(const float2*)&xr[r * 128 + n];
                    yreg[mt][nt][2 * h]     = v.x;
                    yreg[mt][nt][2 * h + 1] = v.y;
                }
    }
    __syncthreads();   // W1 staging dead; Abuf/Hbuf writable

    const float T   = t[0] / 10.0f;    // TIMESCALE = 10
    const float dt0 = g_dt0;

    const unsigned aoff = (unsigned)(((m0 + lrow) * PADK + lcol) * 2);
    const unsigned Ab[2] = { (unsigned)__cvta_generic_to_shared(Abufs[0]) + aoff,
                             (unsigned)__cvta_generic_to_shared(Abufs[1]) + aoff };
    const unsigned Hb[2] = { (unsigned)__cvta_generic_to_shared(Hbufs[0]) + aoff,
                             (unsigned)__cvta_generic_to_shared(Hbufs[1]) + aoff };
    const int browoff = (lane & 7) + ((lane >> 4) << 3);
    const int bcoloff = ((lane >> 3) & 1) * 8;
    const unsigned Bw0 = (unsigned)__cvta_generic_to_shared(Wst2)
                       + (unsigned)(((n0 + browoff) * PADK + bcoloff) * 2);
    const unsigned Bw1 = Bw0 + 16 * PADK * 2;
    const float* bias1 = bstag;
    const float* bias2 = bstag + 128;

    const __nv_bfloat162 C2b[1] = { __float2bfloat162_rn(1.f / 5.f) };
    const __nv_bfloat162 C3b[2] = { __float2bfloat162_rn(3.f / 40.f),
                                    __float2bfloat162_rn(9.f / 40.f) };
    const __nv_bfloat162 C4b[3] = { __float2bfloat162_rn(44.f / 45.f),
                                    __float2bfloat162_rn(-56.f / 15.f),
                                    __float2bfloat162_rn(32.f / 9.f) };
    const __nv_bfloat162 C5b[4] = { __float2bfloat162_rn(19372.f / 6561.f),
                                    __float2bfloat162_rn(-25360.f / 2187.f),
                                    __float2bfloat162_rn(64448.f / 6561.f),
                                    __float2bfloat162_rn(-212.f / 729.f) };
    const __nv_bfloat162 C6b[5] = { __float2bfloat162_rn(9017.f / 3168.f),
                                    __float2bfloat162_rn(-355.f / 33.f),
                                    __float2bfloat162_rn(46732.f / 5247.f),
                                    __float2bfloat162_rn(49.f / 176.f),
                                    __float2bfloat162_rn(-5103.f / 18656.f) };
    const float B1 = 35.f / 384.f, B3 = 500.f / 1113.f, B4 = 125.f / 192.f,
                B5 = -2187.f / 6784.f, B6 = 11.f / 84.f;

    unsigned kp[5][16];                 // k1..k5 packed bf16x2, own 32x32 tile
    float c[2][4][4];

    // skew prologue (R13, proven): m-group 1 burns one dummy GEMM so the two
    // group pipelines anti-phase on the SMSPs.
    if (m0 != 0) {
        gemm_w1(c, Ab[0], wb1, bias1, n0, qn);
    }

    float tt = 0.f;
    int p = 0;
    for (int it = 0; it < 48; it++) {
        float dt = fminf(fmaxf(T - tt, 0.f), dt0);
        if (!(dt > 0.f)) break;
        const unsigned dtb = cvt_bf2u(dt, dt);   // bf16x2(dt), once per step

#define STAGE(NK, COEF, KQ)                                                  \
        build_arg<NK>(Abufs[p], kp, yreg, dtb, COEF, m0, n0, gm, qn);        \
        BARG();                          /* Abuf[p] ready (m-group) */       \
        gemm_w1(c, Ab[p], wb1, bias1, n0, qn);                               \
        store_h(Hbufs[p], c, m0, n0, gm, qn);                                \
        BARG();                          /* Hbuf[p] ready; Abuf[p] free */   \
        gemm_w2(c, Hb[p], Bw0, Bw1, bias2, n0, qn);                          \
        if (KQ >= 0) {                                                       \
            _Pragma("unroll")                                                \
            for (int mt = 0; mt < 2; mt++)                                   \
                _Pragma("unroll")                                            \
                for (int nt = 0; nt < 4; nt++)                               \
                    _Pragma("unroll")                                        \
                    for (int h = 0; h < 2; h++)                              \
                        kp[KQ][(mt * 4 + nt) * 2 + h] =                      \
                            cvt_bf2u(c[mt][nt][2 * h], c[mt][nt][2 * h + 1]);\
        }                                                                    \
        p ^= 1;

        STAGE(0, C2b, 0)
        STAGE(1, C2b, 1)
        STAGE(2, C3b, 2)
        STAGE(3, C4b, 3)
        STAGE(4, C5b, 4)
        STAGE(5, C6b, -1)   // c = k6, stays fp32 in registers
#undef STAGE

        // y += dt*(B1 k1 + B3 k3 + B4 k4 + B5 k5 + B6 k6)  (fp32 math, once
        // per step -- precision-critical, unchanged)
#pragma unroll
        for (int mt = 0; mt < 2; mt++)
#pragma unroll
            for (int nt = 0; nt < 4; nt++)
#pragma unroll
                for (int h = 0; h < 2; h++) {
                    const int id = (mt * 4 + nt) * 2 + h;
                    float u0 = fmaf(B1, lo16f(kp[0][id]),
                               fmaf(B3, lo16f(kp[2][id]),
                               fmaf(B4, lo16f(kp[3][id]),
                               fmaf(B5, lo16f(kp[4][id]),
                                    B6 * c[mt][nt][2 * h]))));
                    float u1 = fmaf(B1, hi16f(kp[0][id]),
                               fmaf(B3, hi16f(kp[2][id]),
                               fmaf(B4, hi16f(kp[3][id]),
                               fmaf(B5, hi16f(kp[4][id]),
                                    B6 * c[mt][nt][2 * h + 1]))));
                    yreg[mt][nt][2 * h]     = fmaf(dt, u0, yreg[mt][nt][2 * h]);
                    yreg[mt][nt][2 * h + 1] = fmaf(dt, u1, yreg[mt][nt][2 * h + 1]);
                }
        tt += dt;
    }

    // ---- out[1] = yT ----
    float* o1 = out + 8192 * 128 + row0 * 128;
#pragma unroll
    for (int mt = 0; mt < 2; mt++)
#pragma unroll
        for (int nt = 0; nt < 4; nt++)
#pragma unroll
            for (int h = 0; h < 2; h++) {
                const int r = m0 + mt * 16 + gm + 8 * h;
                const int n = n0 + nt * 8 + qn * 2;
                float2 v;
                v.x = yreg[mt][nt][2 * h];
                v.y = yreg[mt][nt][2 * h + 1];
                *(float2*)&o1[r * 128 + n] = v;
            }
#undef BARG
}

// ---------------------------------------------------------------------------
// dt0: faithful fp32 port of initial_step_size on x[0]. (unchanged, proven)
// ---------------------------------------------------------------------------
__device__ __forceinline__ float bsum(float v, float* buf, int j) {
    buf[j] = v; __syncthreads();
    for (int s = 64; s > 0; s >>= 1) { if (j < s) buf[j] += buf[j + s]; __syncthreads(); }
    float r = buf[0]; __syncthreads(); return r;
}
__device__ __forceinline__ void mlp128(const float* yin, float* fout, float* hid,
                                       const float* W1, const float* b1,
                                       const float* W2, const float* b2, int j) {
    float acc = 0.f;
    for (int i = 0; i < 128; i++) acc += yin[i] * W1[i * 128 + j];
    hid[j] = tanhf(acc + b1[j]);
    __syncthreads();
    acc = 0.f;
    for (int i = 0; i < 128; i++) acc += hid[i] * W2[i * 128 + j];
    fout[j] = acc + b2[j];
    __syncthreads();
}
__global__ void dt0_kernel(const float* __restrict__ t, const float* __restrict__ x,
                           const float* __restrict__ W1, const float* __restrict__ b1,
                           const float* __restrict__ W2, const float* __restrict__ b2) {
    __shared__ float y0[128], f0v[128], f1v[128], y1s[128], hid[128], buf[128];
    int j = threadIdx.x;
    y0[j] = x[j];
    __syncthreads();
    mlp128(y0, f0v, hid, W1, b1, W2, b2, j);
    float scale = 1.4e-8f + fabsf(y0[j]) * 1.4e-8f;
    float a0 = y0[j] / scale;
    float d0 = sqrtf(bsum(a0 * a0, buf, j));
    float a1 = f0v[j] / scale;
    float d1 = sqrtf(bsum(a1 * a1, buf, j));
    float h0 = (d0 < 1e-5f || d1 < 1e-5f) ? 1e-6f : (0.01f * d0) / d1;
    y1s[j] = y0[j] + h0 * f0v[j];
    __syncthreads();
    mlp128(y1s, f1v, hid, W1, b1, W2, b2, j);
    float a2 = (f1v[j] - f0v[j]) / scale;
    float d2 = sqrtf(bsum(a2 * a2, buf, j)) / h0;
    float h1 = (d1 <= 1e-15f && d2 <= 1e-15f) ? fmaxf(1e-6f, h0 * 1e-3f)
                                              : powf(0.01f / (d1 + d2), 0.2f);
    if (j == 0) g_dt0 = fminf(100.0f * h0, h1);
}

extern "C" void kernel_launch(void* const* d_in, const int* in_sizes, int n_in,
                              void* d_out, int out_size) {
    const float* t  = (const float*)d_in[0];
    const float* x  = (const float*)d_in[1];
    const float* W1 = (const float*)d_in[2];
    const float* b1 = (const float*)d_in[3];
    const float* W2 = (const float*)d_in[4];
    const float* b2 = (const float*)d_in[5];
    float* out = (float*)d_out;

    dt0_kernel<<<1, 128>>>(t, x, W1, b1, W2, b2);

    int smem = 4 * TB + 128 * PADK * 2 + 1024;   // 4 tiles + Wt2 + bstag = 105472 B
    cudaFuncSetAttribute(ode_kernel, cudaFuncAttributeMaxDynamicSharedMemorySize, smem);
    ode_kernel<<<128, 256, smem>>>(t, x, W1, b1, W2, b2, out);
}

// round 17
// speedup vs baseline: 1.6299x; 1.0423x over previous
#include <cuda_runtime.h>
#include <cuda_bf16.h>

// ---------------------------------------------------------------------------
// NeuralODE Dopri5 fused persistent kernel. R17 = R16 + split GEMM2:
//   Each warp's own 32 hidden columns (k-chunks n0/16, n0/16+1 of GEMM2) have
//   their A-fragments IN REGISTERS via the C-frag->A-frag identity (the
//   warp's own tanh outputs). gemm_w2_pre issues those 16 MMAs BEFORE the
//   Hbuf barrier (B from static smem weights, no hazard); gemm_w2_post does
//   the remaining 6 k-chunks after the barrier, skipping own chunks.
//   -> 25% of GEMM2 overlaps the store_h/barrier window; A-ldsm -25%.
// ---------------------------------------------------------------------------

#define PADK 136                       // bf16 row stride (272 B): conflict-free
#define TB   (64 * PADK * 2)           // one 64x128(+pad) bf16 tile = 17408 B
typedef __nv_bfloat16 Row[PADK];

__device__ float g_dt0;

__device__ __forceinline__ unsigned cvt_bf2u(float lo, float hi) {
    unsigned r; asm("cvt.rn.bf16x2.f32 %0, %1, %2;" : "=r"(r) : "f"(hi), "f"(lo)); return r;
}
__device__ __forceinline__ unsigned tanh_bf2(unsigned p) {
    unsigned r; asm("tanh.approx.bf16x2 %0, %1;" : "=r"(r) : "r"(p)); return r;
}
__device__ __forceinline__ float lo16f(unsigned u) { return __uint_as_float(u << 16); }
__device__ __forceinline__ float hi16f(unsigned u) { return __uint_as_float(u & 0xFFFF0000u); }
__device__ __forceinline__ __nv_bfloat162 asbf2(unsigned u) {
    return *reinterpret_cast<__nv_bfloat162*>(&u);
}
__device__ __forceinline__ unsigned hfma2u(unsigned a, unsigned b, unsigned c) {
    __nv_bfloat162 r = __hfma2(asbf2(a), asbf2(b), asbf2(c));
    return *reinterpret_cast<unsigned*>(&r);
}
__device__ __forceinline__ void mma_bf16(float* c, const unsigned* a, const unsigned* b) {
    asm volatile("mma.sync.aligned.m16n8k16.row.col.f32.bf16.bf16.f32 "
                 "{%0,%1,%2,%3}, {%4,%5,%6,%7}, {%8,%9}, {%0,%1,%2,%3};"
                 : "+f"(c[0]), "+f"(c[1]), "+f"(c[2]), "+f"(c[3])
                 : "r"(a[0]), "r"(a[1]), "r"(a[2]), "r"(a[3]), "r"(b[0]), "r"(b[1]));
}
__device__ __forceinline__ void ldsm_x4(unsigned a[4], unsigned addr) {
    asm volatile("ldmatrix.sync.aligned.m8n8.x4.shared.b16 {%0,%1,%2,%3}, [%4];"
                 : "=r"(a[0]), "=r"(a[1]), "=r"(a[2]), "=r"(a[3]) : "r"(addr));
}

// GEMM1: C[32x32] = A[32x128] @ W1t^T + b1. B from registers, bias from smem.
__device__ __forceinline__ void gemm_w1(float c[2][4][4], unsigned abase,
                                        const unsigned (&wb)[4][8][2],
                                        const float* bias, int n0, int qn) {
#pragma unroll
    for (int nt = 0; nt < 4; nt++) {
        const int nb = n0 + nt * 8 + qn * 2;
        float b0 = bias[nb], b1v = bias[nb + 1];
#pragma unroll
        for (int mt = 0; mt < 2; mt++) {
            c[mt][nt][0] = c[mt][nt][2] = b0;
            c[mt][nt][1] = c[mt][nt][3] = b1v;
        }
    }
#pragma unroll
    for (int kk = 0; kk < 8; kk++) {
        unsigned a[2][4];
#pragma unroll
        for (int mt = 0; mt < 2; mt++)
            ldsm_x4(a[mt], abase + mt * (16 * PADK * 2) + kk * 32);
#pragma unroll
        for (int mt = 0; mt < 2; mt++)
#pragma unroll
            for (int nt = 0; nt < 4; nt++)
                mma_bf16(c[mt][nt], a[mt], wb[nt][kk]);
    }
}

// GEMM2 pre-phase: bias init + own 2 k-chunks from REGISTER A-frags (hown).
// No Abuf/Hbuf dependency -> issues before the barrier.
__device__ __forceinline__ void gemm_w2_pre(float c[2][4][4],
                                            const unsigned (&hown)[2][2][4],
                                            unsigned bw0, unsigned bw1, int kd,
                                            const float* bias, int n0, int qn) {
#pragma unroll
    for (int nt = 0; nt < 4; nt++) {
        const int nb = n0 + nt * 8 + qn * 2;
        float b0 = bias[nb], b1v = bias[nb + 1];
#pragma unroll
        for (int mt = 0; mt < 2; mt++) {
            c[mt][nt][0] = c[mt][nt][2] = b0;
            c[mt][nt][1] = c[mt][nt][3] = b1v;
        }
    }
#pragma unroll
    for (int j = 0; j < 2; j++) {
        const unsigned kko = (unsigned)(2 * kd + j);
        unsigned b0[4], b1[4];
        ldsm_x4(b0, bw0 + kko * 32);
        ldsm_x4(b1, bw1 + kko * 32);
#pragma unroll
        for (int mt = 0; mt < 2; mt++) {
            mma_bf16(c[mt][0], hown[mt][j], b0);
            mma_bf16(c[mt][1], hown[mt][j], b0 + 2);
            mma_bf16(c[mt][2], hown[mt][j], b1);
            mma_bf16(c[mt][3], hown[mt][j], b1 + 2);
        }
    }
}

// GEMM2 post-phase: remaining 6 k-chunks via ldsm from Hbuf (skip own pair).
__device__ __forceinline__ void gemm_w2_post(float c[2][4][4], unsigned abase,
                                             unsigned bw0, unsigned bw1, int kd) {
#pragma unroll
    for (int kk = 0; kk < 8; kk++) {
        if ((kk >> 1) == kd) continue;   // warp-uniform skip of own chunks
        unsigned a[2][4], b0[4], b1[4];
#pragma unroll
        for (int mt = 0; mt < 2; mt++)
            ldsm_x4(a[mt], abase + mt * (16 * PADK * 2) + kk * 32);
        ldsm_x4(b0, bw0 + kk * 32);
        ldsm_x4(b1, bw1 + kk * 32);
#pragma unroll
        for (int mt = 0; mt < 2; mt++) {
            mma_bf16(c[mt][0], a[mt], b0);
            mma_bf16(c[mt][1], a[mt], b0 + 2);
            mma_bf16(c[mt][2], a[mt], b1);
            mma_bf16(c[mt][3], a[mt], b1 + 2);
        }
    }
}

// R16 stage arg: Abuf = HFMA2(combo(kp), bf16x2(dt), bf16x2(y)).
template <int NK>
__device__ __forceinline__ void build_arg(Row* Abuf, const unsigned (&kp)[5][16],
                                          const float (&y)[2][4][4],
                                          unsigned dtb, const __nv_bfloat162* kc,
                                          int m0, int n0, int gm, int qn) {
#pragma unroll
    for (int mt = 0; mt < 2; mt++)
#pragma unroll
        for (int nt = 0; nt < 4; nt++)
#pragma unroll
            for (int h = 0; h < 2; h++) {
                const int id = (mt * 4 + nt) * 2 + h;
                const int r = m0 + mt * 16 + gm + 8 * h;
                const int n = n0 + nt * 8 + qn * 2;
                unsigned yb = cvt_bf2u(y[mt][nt][2 * h], y[mt][nt][2 * h + 1]);
                unsigned v;
                if (NK == 0) {
                    v = yb;
                } else {
                    __nv_bfloat162 acc = __hmul2(asbf2(kp[0][id]), kc[0]);
#pragma unroll
                    for (int q = 1; q < NK; q++)
                        acc = __hfma2(asbf2(kp[q][id]), kc[q], acc);
                    v = hfma2u(*reinterpret_cast<unsigned*>(&acc), dtb, yb);
                }
                *(unsigned*)&Abuf[r][n] = v;
            }
}

// tanh + store own H tile; ALSO keep the packed values as GEMM2 A-fragments:
// hown[mt][j][.] covers own k-chunk j (hidden cols n0+16j .. n0+16j+15).
__device__ __forceinline__ void store_h_keep(Row* dst, const float c[2][4][4],
                                             unsigned (&hown)[2][2][4],
                                             int m0, int n0, int gm, int qn) {
#pragma unroll
    for (int mt = 0; mt < 2; mt++)
#pragma unroll
        for (int nt = 0; nt < 4; nt++) {
            const int r = m0 + mt * 16 + gm;
            const int n = n0 + nt * 8 + qn * 2;
            unsigned v0 = tanh_bf2(cvt_bf2u(c[mt][nt][0], c[mt][nt][1]));
            unsigned v1 = tanh_bf2(cvt_bf2u(c[mt][nt][2], c[mt][nt][3]));
            *(unsigned*)&dst[r][n]     = v0;
            *(unsigned*)&dst[r + 8][n] = v1;
            hown[mt][nt >> 1][(nt & 1) * 2 + 0] = v0;  // a0/a2 (row gm)
            hown[mt][nt >> 1][(nt & 1) * 2 + 1] = v1;  // a1/a3 (row gm+8)
        }
}

__global__ void __launch_bounds__(256, 1)
ode_kernel(const float* __restrict__ t, const float* __restrict__ x,
           const float* __restrict__ W1, const float* __restrict__ b1,
           const float* __restrict__ W2, const float* __restrict__ b2,
           float* __restrict__ out) {
    extern __shared__ unsigned char raw[];
    // smem: Abuf0 | Abuf1 | Hbuf0 | Hbuf1 | Wt2 | bstag
    Row* Abufs[2] = { (Row*)(raw + 0 * TB), (Row*)(raw + 1 * TB) };
    Row* Hbufs[2] = { (Row*)(raw + 2 * TB), (Row*)(raw + 3 * TB) };
    Row* Wst2 = (Row*)(raw + 4 * TB);                      // permanent
    float* bstag = (float*)(raw + 4 * TB + 128 * PADK * 2);// 256 floats
    Row* Wst = (Row*)raw;                                  // W1 staging (dead later)

    const int tid  = threadIdx.x;
    const int row0 = blockIdx.x * 64;
    const int lane = tid & 31, warp = tid >> 5;
    const int m0 = (warp & 1) * 32;        // R9/R13 mapping (best)
    const int n0 = (warp >> 1) * 32;       // 4 n-positions
    const int kd = n0 >> 5;                // own GEMM2 k-chunk pair index
    const int gm = lane >> 2;              // 0..7
    const int qn = lane & 3;               // 0..3
    const int barid = 1 + (warp & 1);      // named barrier per m-group (4 warps)
    const int lrow = lane & 15;
    const int lcol = (lane >> 4) * 8;

#define BARG() asm volatile("bar.sync %0, 128;" :: "r"(barid) : "memory")

    // ---- stage W1 (transposed) into tiles 0-1; W2 into permanent Wt2 ----
    for (int idx = tid; idx < 128 * 128; idx += 256) {
        int k = idx >> 7, n = idx & 127;
        Wst[n][k]  = __float2bfloat16(W1[idx]);
        Wst2[n][k] = __float2bfloat16(W2[idx]);
    }
    if (tid < 128) { bstag[tid] = b1[tid]; bstag[128 + tid] = b2[tid]; }
    for (int idx = tid; idx < 64 * 128; idx += 256)
        out[row0 * 128 + idx] = x[row0 * 128 + idx];
    __syncthreads();

    // ---- W1 B-fragments -> registers (64 regs) ----
    unsigned wb1[4][8][2];
#pragma unroll
    for (int nt = 0; nt < 4; nt++) {
        const int n = n0 + nt * 8 + gm;
#pragma unroll
        for (int kk = 0; kk < 8; kk++) {
            const int kb = kk * 16 + qn * 2;
            wb1[nt][kk][0] = *(const unsigned*)&Wst[n][kb];
            wb1[nt][kk][1] = *(const unsigned*)&Wst[n][kb + 8];
        }
    }

    // ---- state y -> registers (C-fragment layout) ----
    float yreg[2][4][4];
    {
        const float* xr = x + row0 * 128;
#pragma unroll
        for (int mt = 0; mt < 2; mt++)
#pragma unroll
            for (int nt = 0; nt < 4; nt++)
#pragma unroll
                for (int h = 0; h < 2; h++) {
                    const int r = m0 + mt * 16 + gm + 8 * h;
                    const int n = n0 + nt * 8 + qn * 2;
                    float2 v = *(const float2*)&xr[r * 128 + n];
                    yreg[mt][nt][2 * h]     = v.x;
                    yreg[mt][nt][2 * h + 1] = v.y;
                }
    }
    __syncthreads();   // W1 staging dead; Abuf/Hbuf writable

    const float T   = t[0] / 10.0f;    // TIMESCALE = 10
    const float dt0 = g_dt0;

    const unsigned aoff = (unsigned)(((m0 + lrow) * PADK + lcol) * 2);
    const unsigned Ab[2] = { (unsigned)__cvta_generic_to_shared(Abufs[0]) + aoff,
                             (unsigned)__cvta_generic_to_shared(Abufs[1]) + aoff };
    const unsigned Hb[2] = { (unsigned)__cvta_generic_to_shared(Hbufs[0]) + aoff,
                             (unsigned)__cvta_generic_to_shared(Hbufs[1]) + aoff };
    const int browoff = (lane & 7) + ((lane >> 4) << 3);
    const int bcoloff = ((lane >> 3) & 1) * 8;
    const unsigned Bw0 = (unsigned)__cvta_generic_to_shared(Wst2)
                       + (unsigned)(((n0 + browoff) * PADK + bcoloff) * 2);
    const unsigned Bw1 = Bw0 + 16 * PADK * 2;
    const float* bias1 = bstag;
    const float* bias2 = bstag + 128;

    const __nv_bfloat162 C2b[1] = { __float2bfloat162_rn(1.f / 5.f) };
    const __nv_bfloat162 C3b[2] = { __float2bfloat162_rn(3.f / 40.f),
                                    __float2bfloat162_rn(9.f / 40.f) };
    const __nv_bfloat162 C4b[3] = { __float2bfloat162_rn(44.f / 45.f),
                                    __float2bfloat162_rn(-56.f / 15.f),
                                    __float2bfloat162_rn(32.f / 9.f) };
    const __nv_bfloat162 C5b[4] = { __float2bfloat162_rn(19372.f / 6561.f),
                                    __float2bfloat162_rn(-25360.f / 2187.f),
                                    __float2bfloat162_rn(64448.f / 6561.f),
                                    __float2bfloat162_rn(-212.f / 729.f) };
    const __nv_bfloat162 C6b[5] = { __float2bfloat162_rn(9017.f / 3168.f),
                                    __float2bfloat162_rn(-355.f / 33.f),
                                    __float2bfloat162_rn(46732.f / 5247.f),
                                    __float2bfloat162_rn(49.f / 176.f),
                                    __float2bfloat162_rn(-5103.f / 18656.f) };
    const float B1 = 35.f / 384.f, B3 = 500.f / 1113.f, B4 = 125.f / 192.f,
                B5 = -2187.f / 6784.f, B6 = 11.f / 84.f;

    unsigned kp[5][16];                 // k1..k5 packed bf16x2, own 32x32 tile
    float c[2][4][4];
    unsigned hown[2][2][4];             // own GEMM2 A-frags (transient)

    // skew prologue (R13, proven)
    if (m0 != 0) {
        gemm_w1(c, Ab[0], wb1, bias1, n0, qn);
    }

    float tt = 0.f;
    int p = 0;
    for (int it = 0; it < 48; it++) {
        float dt = fminf(fmaxf(T - tt, 0.f), dt0);
        if (!(dt > 0.f)) break;
        const unsigned dtb = cvt_bf2u(dt, dt);   // bf16x2(dt), once per step

#define STAGE(NK, COEF, KQ)                                                  \
        build_arg<NK>(Abufs[p], kp, yreg, dtb, COEF, m0, n0, gm, qn);        \
        BARG();                          /* Abuf[p] ready (m-group) */       \
        gemm_w1(c, Ab[p], wb1, bias1, n0, qn);                               \
        store_h_keep(Hbufs[p], c, hown, m0, n0, gm, qn);                     \
        gemm_w2_pre(c, hown, Bw0, Bw1, kd, bias2, n0, qn);                   \
        BARG();                          /* Hbuf[p] ready; Abuf[p] free */   \
        gemm_w2_post(c, Hb[p], Bw0, Bw1, kd);                                \
        if (KQ >= 0) {                                                       \
            _Pragma("unroll")                                                \
            for (int mt = 0; mt < 2; mt++)                                   \
                _Pragma("unroll")                                            \
                for (int nt = 0; nt < 4; nt++)                               \
                    _Pragma("unroll")                                        \
                    for (int h = 0; h < 2; h++)                              \
                        kp[KQ][(mt * 4 + nt) * 2 + h] =                      \
                            cvt_bf2u(c[mt][nt][2 * h], c[mt][nt][2 * h + 1]);\
        }                                                                    \
        p ^= 1;

        STAGE(0, C2b, 0)
        STAGE(1, C2b, 1)
        STAGE(2, C3b, 2)
        STAGE(3, C4b, 3)
        STAGE(4, C5b, 4)
        STAGE(5, C6b, -1)   // c = k6, stays fp32 in registers
#undef STAGE

        // y += dt*(B1 k1 + B3 k3 + B4 k4 + B5 k5 + B6 k6)  (fp32 math)
#pragma unroll
        for (int mt = 0; mt < 2; mt++)
#pragma unroll
            for (int nt = 0; nt < 4; nt++)
#pragma unroll
                for (int h = 0; h < 2; h++) {
                    const int id = (mt * 4 + nt) * 2 + h;
                    float u0 = fmaf(B1, lo16f(kp[0][id]),
                               fmaf(B3, lo16f(kp[2][id]),
                               fmaf(B4, lo16f(kp[3][id]),
                               fmaf(B5, lo16f(kp[4][id]),
                                    B6 * c[mt][nt][2 * h]))));
                    float u1 = fmaf(B1, hi16f(kp[0][id]),
                               fmaf(B3, hi16f(kp[2][id]),
                               fmaf(B4, hi16f(kp[3][id]),
                               fmaf(B5, hi16f(kp[4][id]),
                                    B6 * c[mt][nt][2 * h + 1]))));
                    yreg[mt][nt][2 * h]     = fmaf(dt, u0, yreg[mt][nt][2 * h]);
                    yreg[mt][nt][2 * h + 1] = fmaf(dt, u1, yreg[mt][nt][2 * h + 1]);
                }
        tt += dt;
    }

    // ---- out[1] = yT ----
    float* o1 = out + 8192 * 128 + row0 * 128;
#pragma unroll
    for (int mt = 0; mt < 2; mt++)
#pragma unroll
        for (int nt = 0; nt < 4; nt++)
#pragma unroll
            for (int h = 0; h < 2; h++) {
                const int r = m0 + mt * 16 + gm + 8 * h;
                const int n = n0 + nt * 8 + qn * 2;
                float2 v;
                v.x = yreg[mt][nt][2 * h];
                v.y = yreg[mt][nt][2 * h + 1];
                *(float2*)&o1[r * 128 + n] = v;
            }
#undef BARG
}

// ---------------------------------------------------------------------------
// dt0: faithful fp32 port of initial_step_size on x[0]. (unchanged, proven)
// ---------------------------------------------------------------------------
__device__ __forceinline__ float bsum(float v, float* buf, int j) {
    buf[j] = v; __syncthreads();
    for (int s = 64; s > 0; s >>= 1) { if (j < s) buf[j] += buf[j + s]; __syncthreads(); }
    float r = buf[0]; __syncthreads(); return r;
}
__device__ __forceinline__ void mlp128(const float* yin, float* fout, float* hid,
                                       const float* W1, const float* b1,
                                       const float* W2, const float* b2, int j) {
    float acc = 0.f;
    for (int i = 0; i < 128; i++) acc += yin[i] * W1[i * 128 + j];
    hid[j] = tanhf(acc + b1[j]);
    __syncthreads();
    acc = 0.f;
    for (int i = 0; i < 128; i++) acc += hid[i] * W2[i * 128 + j];
    fout[j] = acc + b2[j];
    __syncthreads();
}
__global__ void dt0_kernel(const float* __restrict__ t, const float* __restrict__ x,
                           const float* __restrict__ W1, const float* __restrict__ b1,
                           const float* __restrict__ W2, const float* __restrict__ b2) {
    __shared__ float y0[128], f0v[128], f1v[128], y1s[128], hid[128], buf[128];
    int j = threadIdx.x;
    y0[j] = x[j];
    __syncthreads();
    mlp128(y0, f0v, hid, W1, b1, W2, b2, j);
    float scale = 1.4e-8f + fabsf(y0[j]) * 1.4e-8f;
    float a0 = y0[j] / scale;
    float d0 = sqrtf(bsum(a0 * a0, buf, j));
    float a1 = f0v[j] / scale;
    float d1 = sqrtf(bsum(a1 * a1, buf, j));
    float h0 = (d0 < 1e-5f || d1 < 1e-5f) ? 1e-6f : (0.01f * d0) / d1;
    y1s[j] = y0[j] + h0 * f0v[j];
    __syncthreads();
    mlp128(y1s, f1v, hid, W1, b1, W2, b2, j);
    float a2 = (f1v[j] - f0v[j]) / scale;
    float d2 = sqrtf(bsum(a2 * a2, buf, j)) / h0;
    float h1 = (d1 <= 1e-15f && d2 <= 1e-15f) ? fmaxf(1e-6f, h0 * 1e-3f)
                                              : powf(0.01f / (d1 + d2), 0.2f);
    if (j == 0) g_dt0 = fminf(100.0f * h0, h1);
}

extern "C" void kernel_launch(void* const* d_in, const int* in_sizes, int n_in,
                              void* d_out, int out_size) {
    const float* t  = (const float*)d_in[0];
    const float* x  = (const float*)d_in[1];
    const float* W1 = (const float*)d_in[2];
    const float* b1 = (const float*)d_in[3];
    const float* W2 = (const float*)d_in[4];
    const float* b2 = (const float*)d_in[5];
    float* out = (float*)d_out;

    dt0_kernel<<<1, 128>>>(t, x, W1, b1, W2, b2);

    int smem = 4 * TB + 128 * PADK * 2 + 1024;   // 4 tiles + Wt2 + bstag = 105472 B
    cudaFuncSetAttribute(ode_kernel, cudaFuncAttributeMaxDynamicSharedMemorySize, smem);
    ode_kernel<<<128, 256, smem>>>(t, x, W1, b1, W2, b2, out);
}